// round 4
// baseline (speedup 1.0000x reference)
#include <cuda_runtime.h>
#include <math.h>

#define BB 8
#define SS 200
#define HH 4
#define DD 64
#define HID 256
#define NBS (BB*SS)   // 1600
#define ITILE 4

// scratch (device globals; no allocation allowed)
__device__ float g_q[NBS*HID];
__device__ float g_kpos[NBS*HID];
__device__ float g_vpos[NBS*HID];
__device__ float g_qo[BB*HH*SS];
__device__ float g_ko[BB*HH*SS];
__device__ float g_qd[BB*HH*SS];
__device__ float g_kd[BB*HH*SS];
__device__ float g_ctx[NBS*HID];
__device__ float g_hs[NBS*HID];

// ---------------------------------------------------------------------------
// Kernel 1: QKV projection. Block = 16 rows x 128 cols of one matrix.
// grid (100, 6): y = mat*2 + colhalf. 256 threads, split-K x4.
// Epilogue on q/k blocks computes the order/dist scalar dot tables.
// ---------------------------------------------------------------------------
__global__ __launch_bounds__(256) void gemm3_kernel(
    const float* __restrict__ x,
    const float* __restrict__ Wq, const float* __restrict__ bq,
    const float* __restrict__ Wk, const float* __restrict__ bk,
    const float* __restrict__ Wv, const float* __restrict__ bv,
    const float* __restrict__ posK, const float* __restrict__ posV,
    const float* __restrict__ order_w, const float* __restrict__ dist_w)
{
    const int r0  = blockIdx.x * 16;
    const int mat = blockIdx.y >> 1;      // 0=q, 1=k, 2=v
    const int hn  = blockIdx.y & 1;       // which 128-col half
    const float* __restrict__ W    = (mat == 0) ? Wq : (mat == 1) ? Wk : Wv;
    const float* __restrict__ bias = (mat == 0) ? bq : (mat == 1) ? bk : bv;

    const int tid = threadIdx.x;
    const int s   = tid >> 6;             // k-slice 0..3 (64 k each)
    const int c   = tid & 63;             // col pair within half
    const int col = hn * 128 + 2 * c;

    __shared__ float xs[HID][16];         // 16KB, x transposed
    __shared__ float red[3][16][128];     // 24KB partials
    __shared__ float fin[16][128];        // 8KB final (for dot epilogue)

    for (int t = tid; t < 16 * HID; t += 256) {
        const int m = t >> 8, g = t & 255;
        xs[g][m] = x[(size_t)(r0 + m) * HID + g];
    }
    __syncthreads();

    float2 acc[16];
    if (s == 0) {
        const float2 b2 = *(const float2*)&bias[col];
        #pragma unroll
        for (int m = 0; m < 16; m++) acc[m] = b2;
    } else {
        #pragma unroll
        for (int m = 0; m < 16; m++) acc[m] = make_float2(0.f, 0.f);
    }

    const float* __restrict__ Wp = W + (size_t)(s * 64) * HID + col;
    const float* __restrict__ xp = &xs[s * 64][0];
    #pragma unroll 4
    for (int gi = 0; gi < 64; gi++) {
        const float2 w = *(const float2*)(Wp + (size_t)gi * HID);
        #pragma unroll
        for (int m = 0; m < 16; m++) {
            const float xv = xp[gi * 16 + m];
            acc[m].x += xv * w.x;
            acc[m].y += xv * w.y;
        }
    }

    if (s > 0) {
        #pragma unroll
        for (int m = 0; m < 16; m++)
            *(float2*)&red[s - 1][m][2 * c] = acc[m];
    }
    __syncthreads();

    if (s == 0) {
        #pragma unroll
        for (int m = 0; m < 16; m++) {
            const float2 p0 = *(const float2*)&red[0][m][2 * c];
            const float2 p1 = *(const float2*)&red[1][m][2 * c];
            const float2 p2 = *(const float2*)&red[2][m][2 * c];
            float2 a = acc[m];
            a.x += p0.x + p1.x + p2.x;
            a.y += p0.y + p1.y + p2.y;
            const size_t gidx = (size_t)(r0 + m) * HID + col;
            if (mat == 0) {
                *(float2*)&g_q[gidx] = a;
                *(float2*)&fin[m][2 * c] = a;
            } else if (mat == 1) {
                const float2 pk = *(const float2*)&posK[gidx];
                float2 kp = make_float2(a.x + pk.x, a.y + pk.y);
                *(float2*)&g_kpos[gidx] = kp;
                *(float2*)&fin[m][2 * c] = a;   // raw k for dots
            } else {
                const float2 pv = *(const float2*)&posV[gidx];
                a.x += pv.x; a.y += pv.y;
                *(float2*)&g_vpos[gidx] = a;
            }
        }
    }
    __syncthreads();

    // epilogue: order/dist dots (q blocks -> qo/qd, k blocks -> ko/kd).
    // Heads in this half: h = 2*hn + hl, using fin cols [hl*64, hl*64+64).
    if (mat < 2) {
        const int w = tid >> 5, l = tid & 31;   // warp w handles rows {w, w+8}
        const int obase = (mat == 1) ? 64 : 0;
        const float ow1 = order_w[obase + l],      ow2 = order_w[obase + 32 + l];
        const float dw1 = dist_w[obase + l],       dw2 = dist_w[obase + 32 + l];
        #pragma unroll
        for (int rr = 0; rr < 2; rr++) {
            const int m = w + rr * 8;
            const int row = r0 + m;
            const int b = row / SS, sidx = row % SS;
            #pragma unroll
            for (int hl = 0; hl < 2; hl++) {
                const float v1 = fin[m][hl * 64 + l];
                const float v2 = fin[m][hl * 64 + 32 + l];
                float ao = v1 * ow1 + v2 * ow2;
                float ad = v1 * dw1 + v2 * dw2;
                #pragma unroll
                for (int off = 16; off; off >>= 1) {
                    ao += __shfl_xor_sync(0xffffffffu, ao, off);
                    ad += __shfl_xor_sync(0xffffffffu, ad, off);
                }
                if (l == 0) {
                    const int h = 2 * hn + hl;
                    const int idx = (b * HH + h) * SS + sidx;
                    if (mat == 0) { g_qo[idx] = ao; g_qd[idx] = ad; }
                    else          { g_ko[idx] = ao; g_kd[idx] = ad; }
                }
            }
        }
    }
}

// ---------------------------------------------------------------------------
// Kernel 2: attention, ITILE=4 query rows per block, 512 threads.
// ---------------------------------------------------------------------------
__global__ __launch_bounds__(512) void attn_kernel(
    const float* __restrict__ timeK, const float* __restrict__ timeV,
    const float* __restrict__ mask,
    const float* __restrict__ p_order_b, const float* __restrict__ p_dist_b,
    const float* __restrict__ p_scalar)
{
    const int tid = threadIdx.x;
    const int blk = blockIdx.x;
    const int b  = blk / (SS / ITILE);
    const int i0 = (blk % (SS / ITILE)) * ITILE;
    const int w = tid >> 5, l = tid & 31;

    __shared__ float sc[ITILE][HH][SS];     // scores -> un-normalized probs
    __shared__ float q_sh[ITILE][HID];
    __shared__ float qos[ITILE][HH], qds[ITILE][HH];
    __shared__ float inv_s[ITILE][HH];
    __shared__ float dl[SS];                // log(|d|+1) table

    for (int t = tid; t < ITILE * HID; t += 512) {
        const int it = t >> 8;
        q_sh[it][t & 255] = g_q[((size_t)(b * SS + i0 + it)) * HID + (t & 255)];
    }
    if (tid < ITILE * HH) {
        const int it = tid >> 2, h = tid & 3;
        qos[it][h] = g_qo[(b * HH + h) * SS + i0 + it];
        qds[it][h] = g_qd[(b * HH + h) * SS + i0 + it];
    }
    if (tid < SS) dl[tid] = __logf((float)tid + 1.f);
    __syncthreads();

    // per-lane fixed q slice: floats [8l, 8l+8)
    float4 q0[ITILE], q1[ITILE];
    #pragma unroll
    for (int it = 0; it < ITILE; it++) {
        q0[it] = *(const float4*)&q_sh[it][l * 8];
        q1[it] = *(const float4*)&q_sh[it][l * 8 + 4];
    }
    const int hh = l >> 3;

    const float* tkb[ITILE];
    #pragma unroll
    for (int it = 0; it < ITILE; it++)
        tkb[it] = timeK + ((size_t)(b * SS + i0 + it)) * SS * HID;

    // ---- phase 1: raw scores  q_i . (timeK_ij + k_j + posK_j) ----
    for (int j = w; j < SS; j += 16) {
        const float4* kp = (const float4*)(g_kpos + (size_t)(b * SS + j) * HID);
        const float4 k0 = kp[2 * l], k1 = kp[2 * l + 1];
        #pragma unroll
        for (int it = 0; it < ITILE; it++) {
            const float4* tk = (const float4*)(tkb[it] + (size_t)j * HID);
            const float4 t0 = tk[2 * l], t1 = tk[2 * l + 1];
            float p = q0[it].x * (t0.x + k0.x) + q0[it].y * (t0.y + k0.y)
                    + q0[it].z * (t0.z + k0.z) + q0[it].w * (t0.w + k0.w)
                    + q1[it].x * (t1.x + k1.x) + q1[it].y * (t1.y + k1.y)
                    + q1[it].z * (t1.z + k1.z) + q1[it].w * (t1.w + k1.w);
            p += __shfl_xor_sync(0xffffffffu, p, 1);
            p += __shfl_xor_sync(0xffffffffu, p, 2);
            p += __shfl_xor_sync(0xffffffffu, p, 4);
            if ((l & 7) == 0) sc[it][hh][j] = p;
        }
    }
    __syncthreads();

    // ---- phase 2: order/dist error terms, scale, mask ----
    const float order_b = *p_order_b;
    const float dist_b  = *p_dist_b;
    const float sc2 = p_scalar[0] * p_scalar[0] * 0.5f;
    for (int idx = tid; idx < ITILE * HH * SS; idx += 512) {
        const int it = idx / (HH * SS);
        const int rem = idx - it * (HH * SS);
        const int h = rem / SS, j = rem - (rem / SS) * SS;
        const int i = i0 + it;
        const float z = qos[it][h] + g_ko[(b * HH + h) * SS + j] + order_b;
        const float zz = (j > i) ? -z : z;     // log-sigmoid via softplus
        const float eo = -(fmaxf(zz, 0.f) + __logf(1.f + __expf(-fabsf(zz))));
        const float gd = dl[abs(j - i)];
        const float pd = qds[it][h] + g_kd[(b * HH + h) * SS + j] + dist_b;
        const float ed = -(gd - pd) * (gd - pd) * sc2;
        sc[it][h][j] = (sc[it][h][j] + eo + ed) * 0.125f
                     + mask[((size_t)b * SS + i) * SS + j];
    }
    __syncthreads();

    // ---- phase 3: softmax (warp per (it,h) pair; 16 warps = 16 pairs) ----
    {
        const int it = w >> 2, h = w & 3;
        float m = -1e30f;
        for (int j = l; j < SS; j += 32) m = fmaxf(m, sc[it][h][j]);
        #pragma unroll
        for (int off = 16; off; off >>= 1)
            m = fmaxf(m, __shfl_xor_sync(0xffffffffu, m, off));
        float sum = 0.f;
        for (int j = l; j < SS; j += 32) {
            const float e = __expf(sc[it][h][j] - m);
            sc[it][h][j] = e;
            sum += e;
        }
        #pragma unroll
        for (int off = 16; off; off >>= 1)
            sum += __shfl_xor_sync(0xffffffffu, sum, off);
        if (l == 0) inv_s[it][h] = 1.f / sum;
    }
    __syncthreads();

    // ---- phase 4: ctx; group g=tid>>8 handles it in {2g, 2g+1} ----
    const int f   = tid & 255;
    const int grp = tid >> 8;
    const int h   = f >> 6;
    const float* tv0 = timeV + ((size_t)(b * SS + i0 + 2 * grp))     * SS * HID + f;
    const float* tv1 = timeV + ((size_t)(b * SS + i0 + 2 * grp + 1)) * SS * HID + f;
    const float* vp  = g_vpos + (size_t)b * SS * HID + f;

    float acc0 = 0.f, acc1 = 0.f;
    #pragma unroll 2
    for (int j = 0; j < SS; j++) {
        const float vpv = vp[(size_t)j * HID];
        acc0 += sc[2 * grp][h][j]     * (tv0[(size_t)j * HID] + vpv);
        acc1 += sc[2 * grp + 1][h][j] * (tv1[(size_t)j * HID] + vpv);
    }
    g_ctx[((size_t)(b * SS + i0 + 2 * grp))     * HID + f] = acc0 * inv_s[2 * grp][h];
    g_ctx[((size_t)(b * SS + i0 + 2 * grp + 1)) * HID + f] = acc1 * inv_s[2 * grp + 1][h];
}

// ---------------------------------------------------------------------------
// Kernel 3a: output projection. Block = 8 rows x 128 cols, 512 threads,
// split-K x8. grid (200, 2). Writes hs = ctx@Wd + bd + x to g_hs.
// ---------------------------------------------------------------------------
__global__ __launch_bounds__(512) void outg_kernel(
    const float* __restrict__ x,
    const float* __restrict__ Wd, const float* __restrict__ bd)
{
    const int r0 = blockIdx.x * 8;
    const int hn = blockIdx.y;
    const int tid = threadIdx.x;
    const int s = tid >> 6;               // k-slice 0..7 (32 k each)
    const int c = tid & 63;
    const int col = hn * 128 + 2 * c;

    __shared__ float cs[HID][8];          // 8KB ctx transposed
    __shared__ float red[7][8][128];      // 28KB

    for (int t = tid; t < 8 * HID; t += 512) {
        const int m = t >> 8, g = t & 255;
        cs[g][m] = g_ctx[(size_t)(r0 + m) * HID + g];
    }
    __syncthreads();

    float2 acc[8];
    if (s == 0) {
        const float2 b2 = *(const float2*)&bd[col];
        #pragma unroll
        for (int m = 0; m < 8; m++) acc[m] = b2;
    } else {
        #pragma unroll
        for (int m = 0; m < 8; m++) acc[m] = make_float2(0.f, 0.f);
    }

    const float* __restrict__ Wp = Wd + (size_t)(s * 32) * HID + col;
    const float* __restrict__ xp = &cs[s * 32][0];
    #pragma unroll 4
    for (int gi = 0; gi < 32; gi++) {
        const float2 w = *(const float2*)(Wp + (size_t)gi * HID);
        #pragma unroll
        for (int m = 0; m < 8; m++) {
            const float xv = xp[gi * 8 + m];
            acc[m].x += xv * w.x;
            acc[m].y += xv * w.y;
        }
    }

    if (s > 0) {
        #pragma unroll
        for (int m = 0; m < 8; m++)
            *(float2*)&red[s - 1][m][2 * c] = acc[m];
    }
    __syncthreads();

    if (s == 0) {
        #pragma unroll
        for (int m = 0; m < 8; m++) {
            float2 a = acc[m];
            #pragma unroll
            for (int p = 0; p < 7; p++) {
                const float2 r = *(const float2*)&red[p][m][2 * c];
                a.x += r.x; a.y += r.y;
            }
            const size_t gidx = (size_t)(r0 + m) * HID + col;
            const float2 xv = *(const float2*)&x[gidx];
            a.x += xv.x; a.y += xv.y;
            *(float2*)&g_hs[gidx] = a;
        }
    }
}

// ---------------------------------------------------------------------------
// Kernel 3b: LayerNorm. Warp per row, 8 rows per block.
// ---------------------------------------------------------------------------
__global__ __launch_bounds__(256) void ln_kernel(
    const float* __restrict__ ln_g, const float* __restrict__ ln_b,
    float* __restrict__ out)
{
    const int w = threadIdx.x >> 5, l = threadIdx.x & 31;
    const int row = blockIdx.x * 8 + w;
    const float* hp = g_hs + (size_t)row * HID;

    const float4 a0 = *(const float4*)&hp[l * 8];
    const float4 a1 = *(const float4*)&hp[l * 8 + 4];
    float s  = a0.x + a0.y + a0.z + a0.w + a1.x + a1.y + a1.z + a1.w;
    float s2 = a0.x*a0.x + a0.y*a0.y + a0.z*a0.z + a0.w*a0.w
             + a1.x*a1.x + a1.y*a1.y + a1.z*a1.z + a1.w*a1.w;
    #pragma unroll
    for (int off = 16; off; off >>= 1) {
        s  += __shfl_xor_sync(0xffffffffu, s,  off);
        s2 += __shfl_xor_sync(0xffffffffu, s2, off);
    }
    const float mu  = s / HID;
    const float rst = rsqrtf(s2 / HID - mu * mu + 1e-12f);

    const float4 g0 = *(const float4*)&ln_g[l * 8];
    const float4 g1 = *(const float4*)&ln_g[l * 8 + 4];
    const float4 b0 = *(const float4*)&ln_b[l * 8];
    const float4 b1 = *(const float4*)&ln_b[l * 8 + 4];
    float4 o0, o1;
    o0.x = (a0.x - mu) * rst * g0.x + b0.x;
    o0.y = (a0.y - mu) * rst * g0.y + b0.y;
    o0.z = (a0.z - mu) * rst * g0.z + b0.z;
    o0.w = (a0.w - mu) * rst * g0.w + b0.w;
    o1.x = (a1.x - mu) * rst * g1.x + b1.x;
    o1.y = (a1.y - mu) * rst * g1.y + b1.y;
    o1.z = (a1.z - mu) * rst * g1.z + b1.z;
    o1.w = (a1.w - mu) * rst * g1.w + b1.w;
    *(float4*)&out[(size_t)row * HID + l * 8]     = o0;
    *(float4*)&out[(size_t)row * HID + l * 8 + 4] = o1;
}

// ---------------------------------------------------------------------------
extern "C" void kernel_launch(void* const* d_in, const int* in_sizes, int n_in,
                              void* d_out, int out_size)
{
    const float* x     = (const float*)d_in[0];
    const float* mask  = (const float*)d_in[1];
    const float* posK  = (const float*)d_in[2];
    const float* posV  = (const float*)d_in[3];
    const float* timeK = (const float*)d_in[4];
    const float* timeV = (const float*)d_in[5];
    const float* Wq = (const float*)d_in[6];  const float* bq = (const float*)d_in[7];
    const float* Wk = (const float*)d_in[8];  const float* bk = (const float*)d_in[9];
    const float* Wv = (const float*)d_in[10]; const float* bv = (const float*)d_in[11];
    const float* ow = (const float*)d_in[12]; const float* ob = (const float*)d_in[13];
    const float* dw = (const float*)d_in[14]; const float* db = (const float*)d_in[15];
    const float* sca = (const float*)d_in[16];
    const float* Wd = (const float*)d_in[17]; const float* bd = (const float*)d_in[18];
    const float* lg = (const float*)d_in[19]; const float* lb = (const float*)d_in[20];

    dim3 g1(NBS / 16, 6);
    gemm3_kernel<<<g1, 256>>>(x, Wq, bq, Wk, bk, Wv, bv, posK, posV, ow, dw);
    attn_kernel<<<NBS / ITILE, 512>>>(timeK, timeV, mask, ob, db, sca);
    dim3 g3(NBS / 8, 2);
    outg_kernel<<<g3, 512>>>(x, Wd, bd);
    ln_kernel<<<NBS / 8, 256>>>(lg, lb, (float*)d_out);
}

// round 5
// speedup vs baseline: 1.0783x; 1.0783x over previous
#include <cuda_runtime.h>
#include <math.h>

#define BB 8
#define SS 200
#define HH 4
#define DD 64
#define HID 256
#define NBS (BB*SS)   // 1600
#define ITILE 2

// scratch (device globals; no allocation allowed)
__device__ float g_q[NBS*HID];
__device__ float g_kpos[NBS*HID];
__device__ float g_vpos[NBS*HID];
__device__ float g_qo[BB*HH*SS];
__device__ float g_ko[BB*HH*SS];
__device__ float g_qd[BB*HH*SS];
__device__ float g_kd[BB*HH*SS];
__device__ float g_ctx[NBS*HID];
__device__ float g_hs[NBS*HID];

// ---------------------------------------------------------------------------
// Kernel 1: QKV projection. Block = 16 rows x 128 cols of one matrix.
// grid (100, 6): y = mat*2 + colhalf. 256 threads, split-K x4.
// Epilogue on q/k blocks computes the order/dist scalar dot tables.
// ---------------------------------------------------------------------------
__global__ __launch_bounds__(256) void gemm3_kernel(
    const float* __restrict__ x,
    const float* __restrict__ Wq, const float* __restrict__ bq,
    const float* __restrict__ Wk, const float* __restrict__ bk,
    const float* __restrict__ Wv, const float* __restrict__ bv,
    const float* __restrict__ posK, const float* __restrict__ posV,
    const float* __restrict__ order_w, const float* __restrict__ dist_w)
{
    const int r0  = blockIdx.x * 16;
    const int mat = blockIdx.y >> 1;      // 0=q, 1=k, 2=v
    const int hn  = blockIdx.y & 1;       // which 128-col half
    const float* __restrict__ W    = (mat == 0) ? Wq : (mat == 1) ? Wk : Wv;
    const float* __restrict__ bias = (mat == 0) ? bq : (mat == 1) ? bk : bv;

    const int tid = threadIdx.x;
    const int s   = tid >> 6;             // k-slice 0..3 (64 k each)
    const int c   = tid & 63;             // col pair within half
    const int col = hn * 128 + 2 * c;

    __shared__ float xs[HID][16];         // 16KB, x transposed
    __shared__ float red[3][16][128];     // 24KB partials
    __shared__ float fin[16][128];        // 8KB final (for dot epilogue)

    for (int t = tid; t < 16 * HID; t += 256) {
        const int m = t >> 8, g = t & 255;
        xs[g][m] = x[(size_t)(r0 + m) * HID + g];
    }
    __syncthreads();

    float2 acc[16];
    if (s == 0) {
        const float2 b2 = *(const float2*)&bias[col];
        #pragma unroll
        for (int m = 0; m < 16; m++) acc[m] = b2;
    } else {
        #pragma unroll
        for (int m = 0; m < 16; m++) acc[m] = make_float2(0.f, 0.f);
    }

    const float* __restrict__ Wp = W + (size_t)(s * 64) * HID + col;
    const float* __restrict__ xp = &xs[s * 64][0];
    #pragma unroll 4
    for (int gi = 0; gi < 64; gi++) {
        const float2 w = *(const float2*)(Wp + (size_t)gi * HID);
        #pragma unroll
        for (int m = 0; m < 16; m++) {
            const float xv = xp[gi * 16 + m];
            acc[m].x += xv * w.x;
            acc[m].y += xv * w.y;
        }
    }

    if (s > 0) {
        #pragma unroll
        for (int m = 0; m < 16; m++)
            *(float2*)&red[s - 1][m][2 * c] = acc[m];
    }
    __syncthreads();

    if (s == 0) {
        #pragma unroll
        for (int m = 0; m < 16; m++) {
            const float2 p0 = *(const float2*)&red[0][m][2 * c];
            const float2 p1 = *(const float2*)&red[1][m][2 * c];
            const float2 p2 = *(const float2*)&red[2][m][2 * c];
            float2 a = acc[m];
            a.x += p0.x + p1.x + p2.x;
            a.y += p0.y + p1.y + p2.y;
            const size_t gidx = (size_t)(r0 + m) * HID + col;
            if (mat == 0) {
                *(float2*)&g_q[gidx] = a;
                *(float2*)&fin[m][2 * c] = a;
            } else if (mat == 1) {
                const float2 pk = *(const float2*)&posK[gidx];
                float2 kp = make_float2(a.x + pk.x, a.y + pk.y);
                *(float2*)&g_kpos[gidx] = kp;
                *(float2*)&fin[m][2 * c] = a;   // raw k for dots
            } else {
                const float2 pv = *(const float2*)&posV[gidx];
                a.x += pv.x; a.y += pv.y;
                *(float2*)&g_vpos[gidx] = a;
            }
        }
    }
    __syncthreads();

    // epilogue: order/dist dots (q blocks -> qo/qd, k blocks -> ko/kd).
    if (mat < 2) {
        const int w = tid >> 5, l = tid & 31;   // warp w handles rows {w, w+8}
        const int obase = (mat == 1) ? 64 : 0;
        const float ow1 = order_w[obase + l],      ow2 = order_w[obase + 32 + l];
        const float dw1 = dist_w[obase + l],       dw2 = dist_w[obase + 32 + l];
        #pragma unroll
        for (int rr = 0; rr < 2; rr++) {
            const int m = w + rr * 8;
            const int row = r0 + m;
            const int b = row / SS, sidx = row % SS;
            #pragma unroll
            for (int hl = 0; hl < 2; hl++) {
                const float v1 = fin[m][hl * 64 + l];
                const float v2 = fin[m][hl * 64 + 32 + l];
                float ao = v1 * ow1 + v2 * ow2;
                float ad = v1 * dw1 + v2 * dw2;
                #pragma unroll
                for (int off = 16; off; off >>= 1) {
                    ao += __shfl_xor_sync(0xffffffffu, ao, off);
                    ad += __shfl_xor_sync(0xffffffffu, ad, off);
                }
                if (l == 0) {
                    const int h = 2 * hn + hl;
                    const int idx = (b * HH + h) * SS + sidx;
                    if (mat == 0) { g_qo[idx] = ao; g_qd[idx] = ad; }
                    else          { g_ko[idx] = ao; g_kd[idx] = ad; }
                }
            }
        }
    }
}

// ---------------------------------------------------------------------------
// Kernel 2: attention, ITILE=2 query rows per block, 256 threads (no spills).
// ---------------------------------------------------------------------------
__global__ __launch_bounds__(256) void attn_kernel(
    const float* __restrict__ timeK, const float* __restrict__ timeV,
    const float* __restrict__ mask,
    const float* __restrict__ p_order_b, const float* __restrict__ p_dist_b,
    const float* __restrict__ p_scalar)
{
    const int tid = threadIdx.x;
    const int blk = blockIdx.x;
    const int b  = blk / (SS / ITILE);
    const int i0 = (blk % (SS / ITILE)) * ITILE;
    const int w = tid >> 5, l = tid & 31;

    __shared__ float sc[ITILE][HH][SS];     // scores -> un-normalized probs
    __shared__ float q_sh[ITILE][HID];
    __shared__ float qos[ITILE][HH], qds[ITILE][HH];
    __shared__ float inv_s[ITILE][HH];
    __shared__ float dl[SS];                // log(|d|+1) table

    #pragma unroll
    for (int it = 0; it < ITILE; it++)
        q_sh[it][tid] = g_q[((size_t)(b * SS + i0 + it)) * HID + tid];
    if (tid < ITILE * HH) {
        const int it = tid >> 2, h = tid & 3;
        qos[it][h] = g_qo[(b * HH + h) * SS + i0 + it];
        qds[it][h] = g_qd[(b * HH + h) * SS + i0 + it];
    }
    if (tid < SS) dl[tid] = __logf((float)tid + 1.f);
    __syncthreads();

    // per-lane fixed q slice: floats [8l, 8l+8)
    float4 q0[ITILE], q1[ITILE];
    #pragma unroll
    for (int it = 0; it < ITILE; it++) {
        q0[it] = *(const float4*)&q_sh[it][l * 8];
        q1[it] = *(const float4*)&q_sh[it][l * 8 + 4];
    }
    const int hh = l >> 3;

    const float* tkb[ITILE];
    #pragma unroll
    for (int it = 0; it < ITILE; it++)
        tkb[it] = timeK + ((size_t)(b * SS + i0 + it)) * SS * HID;

    // ---- phase 1: raw scores  q_i . (timeK_ij + k_j + posK_j) ----
    #pragma unroll 2
    for (int j = w; j < SS; j += 8) {
        const float4* kp = (const float4*)(g_kpos + (size_t)(b * SS + j) * HID);
        const float4 k0 = kp[2 * l], k1 = kp[2 * l + 1];
        #pragma unroll
        for (int it = 0; it < ITILE; it++) {
            const float4* tk = (const float4*)(tkb[it] + (size_t)j * HID);
            const float4 t0 = tk[2 * l], t1 = tk[2 * l + 1];
            float p = q0[it].x * (t0.x + k0.x) + q0[it].y * (t0.y + k0.y)
                    + q0[it].z * (t0.z + k0.z) + q0[it].w * (t0.w + k0.w)
                    + q1[it].x * (t1.x + k1.x) + q1[it].y * (t1.y + k1.y)
                    + q1[it].z * (t1.z + k1.z) + q1[it].w * (t1.w + k1.w);
            p += __shfl_xor_sync(0xffffffffu, p, 1);
            p += __shfl_xor_sync(0xffffffffu, p, 2);
            p += __shfl_xor_sync(0xffffffffu, p, 4);
            if ((l & 7) == 0) sc[it][hh][j] = p;
        }
    }
    __syncthreads();

    // ---- phase 2: order/dist error terms, scale, mask ----
    const float order_b = *p_order_b;
    const float dist_b  = *p_dist_b;
    const float sc2 = p_scalar[0] * p_scalar[0] * 0.5f;
    for (int idx = tid; idx < ITILE * HH * SS; idx += 256) {
        const int it = idx / (HH * SS);
        const int rem = idx - it * (HH * SS);
        const int h = rem / SS, j = rem - (rem / SS) * SS;
        const int i = i0 + it;
        const float z = qos[it][h] + g_ko[(b * HH + h) * SS + j] + order_b;
        const float zz = (j > i) ? -z : z;     // log-sigmoid via softplus
        const float eo = -(fmaxf(zz, 0.f) + __logf(1.f + __expf(-fabsf(zz))));
        const float gd = dl[abs(j - i)];
        const float pd = qds[it][h] + g_kd[(b * HH + h) * SS + j] + dist_b;
        const float ed = -(gd - pd) * (gd - pd) * sc2;
        sc[it][h][j] = (sc[it][h][j] + eo + ed) * 0.125f
                     + mask[((size_t)b * SS + i) * SS + j];
    }
    __syncthreads();

    // ---- phase 3: softmax (warp per (it,h) pair; 8 warps = 8 pairs) ----
    {
        const int it = w >> 2, h = w & 3;
        float m = -1e30f;
        for (int j = l; j < SS; j += 32) m = fmaxf(m, sc[it][h][j]);
        #pragma unroll
        for (int off = 16; off; off >>= 1)
            m = fmaxf(m, __shfl_xor_sync(0xffffffffu, m, off));
        float sum = 0.f;
        for (int j = l; j < SS; j += 32) {
            const float e = __expf(sc[it][h][j] - m);
            sc[it][h][j] = e;
            sum += e;
        }
        #pragma unroll
        for (int off = 16; off; off >>= 1)
            sum += __shfl_xor_sync(0xffffffffu, sum, off);
        if (l == 0) inv_s[it][h] = 1.f / sum;
    }
    __syncthreads();

    // ---- phase 4: ctx ----
    const int f = tid;
    const int h = f >> 6;
    const float* tv0 = timeV + ((size_t)(b * SS + i0))     * SS * HID + f;
    const float* tv1 = timeV + ((size_t)(b * SS + i0 + 1)) * SS * HID + f;
    const float* vp  = g_vpos + (size_t)b * SS * HID + f;

    float acc0 = 0.f, acc1 = 0.f;
    #pragma unroll 2
    for (int j = 0; j < SS; j++) {
        const float vpv = vp[(size_t)j * HID];
        acc0 += sc[0][h][j] * (tv0[(size_t)j * HID] + vpv);
        acc1 += sc[1][h][j] * (tv1[(size_t)j * HID] + vpv);
    }
    g_ctx[((size_t)(b * SS + i0))     * HID + f] = acc0 * inv_s[0][h];
    g_ctx[((size_t)(b * SS + i0 + 1)) * HID + f] = acc1 * inv_s[1][h];
}

// ---------------------------------------------------------------------------
// Kernel 3a: output projection. Block = 8 rows x 128 cols, 256 threads,
// split-K x4. grid (200, 2). Writes hs = ctx@Wd + bd + x to g_hs.
// ---------------------------------------------------------------------------
__global__ __launch_bounds__(256) void outg_kernel(
    const float* __restrict__ x,
    const float* __restrict__ Wd, const float* __restrict__ bd)
{
    const int r0 = blockIdx.x * 8;
    const int hn = blockIdx.y;
    const int tid = threadIdx.x;
    const int s = tid >> 6;               // k-slice 0..3 (64 k each)
    const int c = tid & 63;
    const int col = hn * 128 + 2 * c;

    __shared__ float cs[HID][8];          // 8KB ctx transposed
    __shared__ float red[3][8][128];      // 12KB

    for (int t = tid; t < 8 * HID; t += 256) {
        const int m = t >> 8, g = t & 255;
        cs[g][m] = g_ctx[(size_t)(r0 + m) * HID + g];
    }
    __syncthreads();

    float2 acc[8];
    if (s == 0) {
        const float2 b2 = *(const float2*)&bd[col];
        #pragma unroll
        for (int m = 0; m < 8; m++) acc[m] = b2;
    } else {
        #pragma unroll
        for (int m = 0; m < 8; m++) acc[m] = make_float2(0.f, 0.f);
    }

    const float* __restrict__ Wp = Wd + (size_t)(s * 64) * HID + col;
    const float* __restrict__ xp = &cs[s * 64][0];
    #pragma unroll 4
    for (int gi = 0; gi < 64; gi++) {
        const float2 w = *(const float2*)(Wp + (size_t)gi * HID);
        #pragma unroll
        for (int m = 0; m < 8; m++) {
            const float xv = xp[gi * 8 + m];
            acc[m].x += xv * w.x;
            acc[m].y += xv * w.y;
        }
    }

    if (s > 0) {
        #pragma unroll
        for (int m = 0; m < 8; m++)
            *(float2*)&red[s - 1][m][2 * c] = acc[m];
    }
    __syncthreads();

    if (s == 0) {
        #pragma unroll
        for (int m = 0; m < 8; m++) {
            const float2 p0 = *(const float2*)&red[0][m][2 * c];
            const float2 p1 = *(const float2*)&red[1][m][2 * c];
            const float2 p2 = *(const float2*)&red[2][m][2 * c];
            float2 a = acc[m];
            a.x += p0.x + p1.x + p2.x;
            a.y += p0.y + p1.y + p2.y;
            const size_t gidx = (size_t)(r0 + m) * HID + col;
            const float2 xv = *(const float2*)&x[gidx];
            a.x += xv.x; a.y += xv.y;
            *(float2*)&g_hs[gidx] = a;
        }
    }
}

// ---------------------------------------------------------------------------
// Kernel 3b: LayerNorm. Warp per row, 8 rows per block.
// ---------------------------------------------------------------------------
__global__ __launch_bounds__(256) void ln_kernel(
    const float* __restrict__ ln_g, const float* __restrict__ ln_b,
    float* __restrict__ out)
{
    const int w = threadIdx.x >> 5, l = threadIdx.x & 31;
    const int row = blockIdx.x * 8 + w;
    const float* hp = g_hs + (size_t)row * HID;

    const float4 a0 = *(const float4*)&hp[l * 8];
    const float4 a1 = *(const float4*)&hp[l * 8 + 4];
    float s  = a0.x + a0.y + a0.z + a0.w + a1.x + a1.y + a1.z + a1.w;
    float s2 = a0.x*a0.x + a0.y*a0.y + a0.z*a0.z + a0.w*a0.w
             + a1.x*a1.x + a1.y*a1.y + a1.z*a1.z + a1.w*a1.w;
    #pragma unroll
    for (int off = 16; off; off >>= 1) {
        s  += __shfl_xor_sync(0xffffffffu, s,  off);
        s2 += __shfl_xor_sync(0xffffffffu, s2, off);
    }
    const float mu  = s / HID;
    const float rst = rsqrtf(s2 / HID - mu * mu + 1e-12f);

    const float4 g0 = *(const float4*)&ln_g[l * 8];
    const float4 g1 = *(const float4*)&ln_g[l * 8 + 4];
    const float4 b0 = *(const float4*)&ln_b[l * 8];
    const float4 b1 = *(const float4*)&ln_b[l * 8 + 4];
    float4 o0, o1;
    o0.x = (a0.x - mu) * rst * g0.x + b0.x;
    o0.y = (a0.y - mu) * rst * g0.y + b0.y;
    o0.z = (a0.z - mu) * rst * g0.z + b0.z;
    o0.w = (a0.w - mu) * rst * g0.w + b0.w;
    o1.x = (a1.x - mu) * rst * g1.x + b1.x;
    o1.y = (a1.y - mu) * rst * g1.y + b1.y;
    o1.z = (a1.z - mu) * rst * g1.z + b1.z;
    o1.w = (a1.w - mu) * rst * g1.w + b1.w;
    *(float4*)&out[(size_t)row * HID + l * 8]     = o0;
    *(float4*)&out[(size_t)row * HID + l * 8 + 4] = o1;
}

// ---------------------------------------------------------------------------
extern "C" void kernel_launch(void* const* d_in, const int* in_sizes, int n_in,
                              void* d_out, int out_size)
{
    const float* x     = (const float*)d_in[0];
    const float* mask  = (const float*)d_in[1];
    const float* posK  = (const float*)d_in[2];
    const float* posV  = (const float*)d_in[3];
    const float* timeK = (const float*)d_in[4];
    const float* timeV = (const float*)d_in[5];
    const float* Wq = (const float*)d_in[6];  const float* bq = (const float*)d_in[7];
    const float* Wk = (const float*)d_in[8];  const float* bk = (const float*)d_in[9];
    const float* Wv = (const float*)d_in[10]; const float* bv = (const float*)d_in[11];
    const float* ow = (const float*)d_in[12]; const float* ob = (const float*)d_in[13];
    const float* dw = (const float*)d_in[14]; const float* db = (const float*)d_in[15];
    const float* sca = (const float*)d_in[16];
    const float* Wd = (const float*)d_in[17]; const float* bd = (const float*)d_in[18];
    const float* lg = (const float*)d_in[19]; const float* lb = (const float*)d_in[20];

    dim3 g1(NBS / 16, 6);
    gemm3_kernel<<<g1, 256>>>(x, Wq, bq, Wk, bk, Wv, bv, posK, posV, ow, dw);
    attn_kernel<<<NBS / ITILE, 256>>>(timeK, timeV, mask, ob, db, sca);
    dim3 g3(NBS / 8, 2);
    outg_kernel<<<g3, 256>>>(x, Wd, bd);
    ln_kernel<<<NBS / 8, 256>>>(lg, lb, (float*)d_out);
}

// round 6
// speedup vs baseline: 1.3722x; 1.2726x over previous
#include <cuda_runtime.h>
#include <math.h>

#define BB 8
#define SS 200
#define HH 4
#define DD 64
#define HID 256
#define NBS (BB*SS)   // 1600

// scratch (device globals; no allocation allowed)
__device__ float g_q[NBS*HID];
__device__ float g_k[NBS*HID];
__device__ float g_kpos[NBS*HID];
__device__ float g_vpos[NBS*HID];
__device__ float g_qo[BB*HH*SS];
__device__ float g_ko[BB*HH*SS];
__device__ float g_qd[BB*HH*SS];
__device__ float g_kd[BB*HH*SS];
__device__ float g_probs[NBS*HH*SS];   // normalized probs, [b][i][h][j]
__device__ float g_ctx[NBS*HID];

// ---------------------------------------------------------------------------
// Kernel 1: one (8-row, matrix) tile per block; split-K x4 inside the block.
// Thread (s=tid/64, c=tid%64) accumulates 8 rows x 4 cols over 64 k-values.
// (round-3 proven version)
// ---------------------------------------------------------------------------
__global__ __launch_bounds__(256) void gemm3_kernel(
    const float* __restrict__ x,
    const float* __restrict__ Wq, const float* __restrict__ bq,
    const float* __restrict__ Wk, const float* __restrict__ bk,
    const float* __restrict__ Wv, const float* __restrict__ bv,
    const float* __restrict__ posV)
{
    const int r0  = blockIdx.x * 8;
    const int mat = blockIdx.y;
    const float* __restrict__ W    = (mat == 0) ? Wq : (mat == 1) ? Wk : Wv;
    const float* __restrict__ bias = (mat == 0) ? bq : (mat == 1) ? bk : bv;

    const int tid = threadIdx.x;
    const int s   = tid >> 6;
    const int c   = tid & 63;

    __shared__ float xs[HID][8];
    __shared__ float red[3][8][HID];

    for (int t = tid; t < 8 * HID; t += 256) {
        const int m = t >> 8, g = t & 255;
        xs[g][m] = x[(r0 + m) * HID + g];
    }
    __syncthreads();

    float4 acc[8];
    if (s == 0) {
        const float4 b4 = *(const float4*)&bias[4 * c];
        #pragma unroll
        for (int m = 0; m < 8; m++) acc[m] = b4;
    } else {
        #pragma unroll
        for (int m = 0; m < 8; m++) acc[m] = make_float4(0.f, 0.f, 0.f, 0.f);
    }

    const float* __restrict__ Wp = W + (size_t)(s * 64) * HID + 4 * c;
    const float* __restrict__ xp = &xs[s * 64][0];
    #pragma unroll 4
    for (int gi = 0; gi < 64; gi++) {
        const float4 w = *(const float4*)(Wp + (size_t)gi * HID);
        #pragma unroll
        for (int m = 0; m < 8; m++) {
            const float xv = xp[gi * 8 + m];
            acc[m].x += xv * w.x; acc[m].y += xv * w.y;
            acc[m].z += xv * w.z; acc[m].w += xv * w.w;
        }
    }

    if (s > 0) {
        #pragma unroll
        for (int m = 0; m < 8; m++)
            *(float4*)&red[s - 1][m][4 * c] = acc[m];
    }
    __syncthreads();

    if (s == 0) {
        #pragma unroll
        for (int m = 0; m < 8; m++) {
            const float4 r0v = *(const float4*)&red[0][m][4 * c];
            const float4 r1v = *(const float4*)&red[1][m][4 * c];
            const float4 r2v = *(const float4*)&red[2][m][4 * c];
            float4 a = acc[m];
            a.x += r0v.x + r1v.x + r2v.x;
            a.y += r0v.y + r1v.y + r2v.y;
            a.z += r0v.z + r1v.z + r2v.z;
            a.w += r0v.w + r1v.w + r2v.w;
            const int row = r0 + m;
            if (mat == 0) {
                *(float4*)&g_q[(size_t)row * HID + 4 * c] = a;
            } else if (mat == 1) {
                *(float4*)&g_k[(size_t)row * HID + 4 * c] = a;
            } else {
                const float4 pv = *(const float4*)&posV[(size_t)row * HID + 4 * c];
                a.x += pv.x; a.y += pv.y; a.z += pv.z; a.w += pv.w;
                *(float4*)&g_vpos[(size_t)row * HID + 4 * c] = a;
            }
        }
    }
}

// ---------------------------------------------------------------------------
// Kernel 1b: kpos = k + posK; order/dist scalar dot tables. 8 rows/block.
// ---------------------------------------------------------------------------
__global__ __launch_bounds__(256) void post_kernel(
    const float* __restrict__ posK,
    const float* __restrict__ order_w, const float* __restrict__ dist_w)
{
    const int f  = threadIdx.x;
    const int r0 = blockIdx.x * 8;

    __shared__ float qs[8][HID];
    __shared__ float ks[8][HID];

    #pragma unroll
    for (int m = 0; m < 8; m++) {
        const int row = r0 + m;
        const float kv = g_k[(size_t)row * HID + f];
        qs[m][f] = g_q[(size_t)row * HID + f];
        ks[m][f] = kv;
        g_kpos[(size_t)row * HID + f] = kv + posK[(size_t)row * HID + f];
    }
    __syncthreads();

    const int w = f >> 5, l = f & 31;
    const int row = r0 + w;
    const int b = row / SS, sidx = row % SS;
    #pragma unroll
    for (int h = 0; h < HH; h++) {
        float qo = qs[w][h*64 + l] * order_w[l]      + qs[w][h*64 + 32 + l] * order_w[32 + l];
        float qd = qs[w][h*64 + l] * dist_w[l]       + qs[w][h*64 + 32 + l] * dist_w[32 + l];
        float ko = ks[w][h*64 + l] * order_w[64 + l] + ks[w][h*64 + 32 + l] * order_w[96 + l];
        float kd = ks[w][h*64 + l] * dist_w[64 + l]  + ks[w][h*64 + 32 + l] * dist_w[96 + l];
        #pragma unroll
        for (int off = 16; off; off >>= 1) {
            qo += __shfl_xor_sync(0xffffffffu, qo, off);
            qd += __shfl_xor_sync(0xffffffffu, qd, off);
            ko += __shfl_xor_sync(0xffffffffu, ko, off);
            kd += __shfl_xor_sync(0xffffffffu, kd, off);
        }
        if (l == 0) {
            const int idx = (b * HH + h) * SS + sidx;
            g_qo[idx] = qo; g_qd[idx] = qd; g_ko[idx] = ko; g_kd[idx] = kd;
        }
    }
}

// ---------------------------------------------------------------------------
// Kernel 2a: scores + softmax. ITILE=2 rows/block, 256 threads, grid 800.
// Streams timeK. Writes normalized probs to g_probs[b][i][h][j].
// ---------------------------------------------------------------------------
#define ITA 2
__global__ __launch_bounds__(256) void score_kernel(
    const float* __restrict__ timeK,
    const float* __restrict__ mask,
    const float* __restrict__ p_order_b, const float* __restrict__ p_dist_b,
    const float* __restrict__ p_scalar)
{
    const int tid = threadIdx.x;
    const int blk = blockIdx.x;
    const int b  = blk / (SS / ITA);
    const int i0 = (blk % (SS / ITA)) * ITA;
    const int w = tid >> 5, l = tid & 31;

    __shared__ float sc[ITA][HH][SS];
    __shared__ float q_sh[ITA][HID];
    __shared__ float qos[ITA][HH], qds[ITA][HH];
    __shared__ float inv_s[ITA][HH];
    __shared__ float dl[SS];

    #pragma unroll
    for (int it = 0; it < ITA; it++)
        q_sh[it][tid] = g_q[((size_t)(b * SS + i0 + it)) * HID + tid];
    if (tid < ITA * HH) {
        const int it = tid >> 2, h = tid & 3;
        qos[it][h] = g_qo[(b * HH + h) * SS + i0 + it];
        qds[it][h] = g_qd[(b * HH + h) * SS + i0 + it];
    }
    if (tid < SS) dl[tid] = __logf((float)tid + 1.f);
    __syncthreads();

    float4 q0[ITA], q1[ITA];
    #pragma unroll
    for (int it = 0; it < ITA; it++) {
        q0[it] = *(const float4*)&q_sh[it][l * 8];
        q1[it] = *(const float4*)&q_sh[it][l * 8 + 4];
    }
    const int hh = l >> 3;

    const float* tk0 = timeK + ((size_t)(b * SS + i0))     * SS * HID;
    const float* tk1 = timeK + ((size_t)(b * SS + i0 + 1)) * SS * HID;
    const float* kpb = g_kpos + (size_t)b * SS * HID;

    // ---- phase 1: two j's per warp iteration for deeper MLP ----
    for (int j = w; j < SS; j += 16) {
        const int j2 = j + 8;
        const bool has2 = (j2 < SS);
        const float4* kp  = (const float4*)(kpb + (size_t)j * HID);
        const float4 ka0 = kp[2 * l], ka1 = kp[2 * l + 1];
        const float4* ta0 = (const float4*)(tk0 + (size_t)j * HID);
        const float4* ta1 = (const float4*)(tk1 + (size_t)j * HID);
        const float4 a00 = ta0[2 * l], a01 = ta0[2 * l + 1];
        const float4 a10 = ta1[2 * l], a11 = ta1[2 * l + 1];

        float4 kb0, kb1, b00, b01, b10, b11;
        if (has2) {
            const float4* kq  = (const float4*)(kpb + (size_t)j2 * HID);
            kb0 = kq[2 * l]; kb1 = kq[2 * l + 1];
            const float4* tb0 = (const float4*)(tk0 + (size_t)j2 * HID);
            const float4* tb1 = (const float4*)(tk1 + (size_t)j2 * HID);
            b00 = tb0[2 * l]; b01 = tb0[2 * l + 1];
            b10 = tb1[2 * l]; b11 = tb1[2 * l + 1];
        }

        float p0 = q0[0].x * (a00.x + ka0.x) + q0[0].y * (a00.y + ka0.y)
                 + q0[0].z * (a00.z + ka0.z) + q0[0].w * (a00.w + ka0.w)
                 + q1[0].x * (a01.x + ka1.x) + q1[0].y * (a01.y + ka1.y)
                 + q1[0].z * (a01.z + ka1.z) + q1[0].w * (a01.w + ka1.w);
        float p1 = q0[1].x * (a10.x + ka0.x) + q0[1].y * (a10.y + ka0.y)
                 + q0[1].z * (a10.z + ka0.z) + q0[1].w * (a10.w + ka0.w)
                 + q1[1].x * (a11.x + ka1.x) + q1[1].y * (a11.y + ka1.y)
                 + q1[1].z * (a11.z + ka1.z) + q1[1].w * (a11.w + ka1.w);
        p0 += __shfl_xor_sync(0xffffffffu, p0, 1);
        p0 += __shfl_xor_sync(0xffffffffu, p0, 2);
        p0 += __shfl_xor_sync(0xffffffffu, p0, 4);
        p1 += __shfl_xor_sync(0xffffffffu, p1, 1);
        p1 += __shfl_xor_sync(0xffffffffu, p1, 2);
        p1 += __shfl_xor_sync(0xffffffffu, p1, 4);
        if ((l & 7) == 0) { sc[0][hh][j] = p0; sc[1][hh][j] = p1; }

        if (has2) {
            float r0 = q0[0].x * (b00.x + kb0.x) + q0[0].y * (b00.y + kb0.y)
                     + q0[0].z * (b00.z + kb0.z) + q0[0].w * (b00.w + kb0.w)
                     + q1[0].x * (b01.x + kb1.x) + q1[0].y * (b01.y + kb1.y)
                     + q1[0].z * (b01.z + kb1.z) + q1[0].w * (b01.w + kb1.w);
            float r1 = q0[1].x * (b10.x + kb0.x) + q0[1].y * (b10.y + kb0.y)
                     + q0[1].z * (b10.z + kb0.z) + q0[1].w * (b10.w + kb0.w)
                     + q1[1].x * (b11.x + kb1.x) + q1[1].y * (b11.y + kb1.y)
                     + q1[1].z * (b11.z + kb1.z) + q1[1].w * (b11.w + kb1.w);
            r0 += __shfl_xor_sync(0xffffffffu, r0, 1);
            r0 += __shfl_xor_sync(0xffffffffu, r0, 2);
            r0 += __shfl_xor_sync(0xffffffffu, r0, 4);
            r1 += __shfl_xor_sync(0xffffffffu, r1, 1);
            r1 += __shfl_xor_sync(0xffffffffu, r1, 2);
            r1 += __shfl_xor_sync(0xffffffffu, r1, 4);
            if ((l & 7) == 0) { sc[0][hh][j2] = r0; sc[1][hh][j2] = r1; }
        }
    }
    __syncthreads();

    // ---- phase 2: order/dist error terms, scale, mask ----
    const float order_b = *p_order_b;
    const float dist_b  = *p_dist_b;
    const float sc2 = p_scalar[0] * p_scalar[0] * 0.5f;
    for (int idx = tid; idx < ITA * HH * SS; idx += 256) {
        const int it = idx / (HH * SS);
        const int rem = idx - it * (HH * SS);
        const int h = rem / SS, j = rem - (rem / SS) * SS;
        const int i = i0 + it;
        const float z = qos[it][h] + g_ko[(b * HH + h) * SS + j] + order_b;
        const float zz = (j > i) ? -z : z;     // log-sigmoid via softplus
        const float eo = -(fmaxf(zz, 0.f) + __logf(1.f + __expf(-fabsf(zz))));
        const float gd = dl[abs(j - i)];
        const float pd = qds[it][h] + g_kd[(b * HH + h) * SS + j] + dist_b;
        const float ed = -(gd - pd) * (gd - pd) * sc2;
        sc[it][h][j] = (sc[it][h][j] + eo + ed) * 0.125f
                     + mask[((size_t)b * SS + i) * SS + j];
    }
    __syncthreads();

    // ---- phase 3: softmax (warp per (it,h) pair; 8 warps = 8 pairs) ----
    {
        const int it = w >> 2, h = w & 3;
        float m = -1e30f;
        for (int j = l; j < SS; j += 32) m = fmaxf(m, sc[it][h][j]);
        #pragma unroll
        for (int off = 16; off; off >>= 1)
            m = fmaxf(m, __shfl_xor_sync(0xffffffffu, m, off));
        float sum = 0.f;
        for (int j = l; j < SS; j += 32) {
            const float e = __expf(sc[it][h][j] - m);
            sc[it][h][j] = e;
            sum += e;
        }
        #pragma unroll
        for (int off = 16; off; off >>= 1)
            sum += __shfl_xor_sync(0xffffffffu, sum, off);
        if (l == 0) inv_s[it][h] = 1.f / sum;
    }
    __syncthreads();

    // ---- write normalized probs ----
    for (int idx = tid; idx < ITA * HH * SS; idx += 256) {
        const int it = idx / (HH * SS);
        const int rem = idx - it * (HH * SS);
        const int h = rem / SS, j = rem - (rem / SS) * SS;
        g_probs[((size_t)(b * SS + i0 + it) * HH + h) * SS + j]
            = sc[it][h][j] * inv_s[it][h];
    }
}

// ---------------------------------------------------------------------------
// Kernel 2b: ctx accumulation. ITILE=4 rows/block, 256 threads, grid 400.
// Thread = (i-row, f-quad). Streams timeV + vpos with float4 FMAs.
// ---------------------------------------------------------------------------
#define ITB 4
__global__ __launch_bounds__(256) void ctx_kernel(
    const float* __restrict__ timeV)
{
    const int tid = threadIdx.x;
    const int blk = blockIdx.x;
    const int b  = blk / (SS / ITB);
    const int i0 = (blk % (SS / ITB)) * ITB;

    const int it = tid >> 6;          // i-row 0..3
    const int fq = tid & 63;          // float4 index; f = 4*fq
    const int h  = fq >> 4;           // head of this f-quad

    __shared__ float pr[ITB][HH * SS];   // 12.8KB

    for (int t = tid; t < ITB * HH * SS; t += 256) {
        const int k = t / (HH * SS);
        const int rem = t - k * (HH * SS);
        pr[k][rem] = g_probs[((size_t)(b * SS + i0 + k) * HH) * SS + rem];
    }
    __syncthreads();

    const float4* tv = (const float4*)(timeV + ((size_t)(b * SS + i0 + it)) * SS * HID) + fq;
    const float4* vp = (const float4*)(g_vpos + (size_t)b * SS * HID) + fq;
    const float* prow = &pr[it][h * SS];

    float4 acc = make_float4(0.f, 0.f, 0.f, 0.f);
    #pragma unroll 4
    for (int j = 0; j < SS; j++) {
        const float p = prow[j];
        const float4 t4 = tv[(size_t)j * (HID / 4)];
        const float4 v4 = vp[(size_t)j * (HID / 4)];
        acc.x += p * (t4.x + v4.x);
        acc.y += p * (t4.y + v4.y);
        acc.z += p * (t4.z + v4.z);
        acc.w += p * (t4.w + v4.w);
    }
    *(float4*)&g_ctx[((size_t)(b * SS + i0 + it)) * HID + 4 * fq] = acc;
}

// ---------------------------------------------------------------------------
// Kernel 3: output projection, 4 rows/block (grid 400) + residual + LN.
// ---------------------------------------------------------------------------
__global__ __launch_bounds__(256) void outln_kernel(
    const float* __restrict__ x,
    const float* __restrict__ Wd, const float* __restrict__ bd,
    const float* __restrict__ ln_g, const float* __restrict__ ln_b,
    float* __restrict__ out)
{
    const int r0  = blockIdx.x * 4;
    const int tid = threadIdx.x;
    const int s   = tid >> 6;
    const int c   = tid & 63;

    __shared__ float cs[HID][4];
    __shared__ float red[3][4][HID];
    __shared__ float hsm[4][HID];
    __shared__ float mu[4], rstd[4];

    for (int t = tid; t < 4 * HID; t += 256) {
        const int m = t >> 8, g = t & 255;
        cs[g][m] = g_ctx[(size_t)(r0 + m) * HID + g];
    }
    __syncthreads();

    float4 acc[4];
    if (s == 0) {
        const float4 b4 = *(const float4*)&bd[4 * c];
        #pragma unroll
        for (int m = 0; m < 4; m++) acc[m] = b4;
    } else {
        #pragma unroll
        for (int m = 0; m < 4; m++) acc[m] = make_float4(0.f, 0.f, 0.f, 0.f);
    }

    const float* __restrict__ Wp = Wd + (size_t)(s * 64) * HID + 4 * c;
    const float* __restrict__ xp = &cs[s * 64][0];
    #pragma unroll 4
    for (int gi = 0; gi < 64; gi++) {
        const float4 w = *(const float4*)(Wp + (size_t)gi * HID);
        #pragma unroll
        for (int m = 0; m < 4; m++) {
            const float xv = xp[gi * 4 + m];
            acc[m].x += xv * w.x; acc[m].y += xv * w.y;
            acc[m].z += xv * w.z; acc[m].w += xv * w.w;
        }
    }

    if (s > 0) {
        #pragma unroll
        for (int m = 0; m < 4; m++)
            *(float4*)&red[s - 1][m][4 * c] = acc[m];
    }
    __syncthreads();

    if (s == 0) {
        #pragma unroll
        for (int m = 0; m < 4; m++) {
            const float4 p0 = *(const float4*)&red[0][m][4 * c];
            const float4 p1 = *(const float4*)&red[1][m][4 * c];
            const float4 p2 = *(const float4*)&red[2][m][4 * c];
            const float4 xv = *(const float4*)&x[(size_t)(r0 + m) * HID + 4 * c];
            float4 a = acc[m];
            a.x += p0.x + p1.x + p2.x + xv.x;
            a.y += p0.y + p1.y + p2.y + xv.y;
            a.z += p0.z + p1.z + p2.z + xv.z;
            a.w += p0.w + p1.w + p2.w + xv.w;
            *(float4*)&hsm[m][4 * c] = a;
        }
    }
    __syncthreads();

    const int w = tid >> 5, l = tid & 31;
    if (w < 4) {
        float sum = 0.f, sum2 = 0.f;
        #pragma unroll
        for (int t = 0; t < 8; t++) {
            const float v = hsm[w][l + 32 * t];
            sum += v; sum2 += v * v;
        }
        #pragma unroll
        for (int off = 16; off; off >>= 1) {
            sum  += __shfl_xor_sync(0xffffffffu, sum,  off);
            sum2 += __shfl_xor_sync(0xffffffffu, sum2, off);
        }
        if (l == 0) {
            const float m_  = sum / HID;
            const float var = sum2 / HID - m_ * m_;
            mu[w]   = m_;
            rstd[w] = rsqrtf(var + 1e-12f);
        }
    }
    __syncthreads();

    const int f = tid;
    const float gf = ln_g[f], bf = ln_b[f];
    #pragma unroll
    for (int m = 0; m < 4; m++)
        out[(size_t)(r0 + m) * HID + f] = (hsm[m][f] - mu[m]) * rstd[m] * gf + bf;
}

// ---------------------------------------------------------------------------
extern "C" void kernel_launch(void* const* d_in, const int* in_sizes, int n_in,
                              void* d_out, int out_size)
{
    const float* x     = (const float*)d_in[0];
    const float* mask  = (const float*)d_in[1];
    const float* posK  = (const float*)d_in[2];
    const float* posV  = (const float*)d_in[3];
    const float* timeK = (const float*)d_in[4];
    const float* timeV = (const float*)d_in[5];
    const float* Wq = (const float*)d_in[6];  const float* bq = (const float*)d_in[7];
    const float* Wk = (const float*)d_in[8];  const float* bk = (const float*)d_in[9];
    const float* Wv = (const float*)d_in[10]; const float* bv = (const float*)d_in[11];
    const float* ow = (const float*)d_in[12]; const float* ob = (const float*)d_in[13];
    const float* dw = (const float*)d_in[14]; const float* db = (const float*)d_in[15];
    const float* sca = (const float*)d_in[16];
    const float* Wd = (const float*)d_in[17]; const float* bd = (const float*)d_in[18];
    const float* lg = (const float*)d_in[19]; const float* lb = (const float*)d_in[20];

    dim3 g1(NBS / 8, 3);
    gemm3_kernel<<<g1, 256>>>(x, Wq, bq, Wk, bk, Wv, bv, posV);
    post_kernel<<<NBS / 8, 256>>>(posK, ow, dw);
    score_kernel<<<NBS / ITA, 256>>>(timeK, mask, ob, db, sca);
    ctx_kernel<<<NBS / ITB, 256>>>(timeV);
    outln_kernel<<<NBS / 4, 256>>>(x, Wd, bd, lg, lb, (float*)d_out);
}

// round 7
// speedup vs baseline: 1.4316x; 1.0433x over previous
#include <cuda_runtime.h>
#include <math.h>

#define BB 8
#define SS 200
#define HH 4
#define DD 64
#define HID 256
#define NBS (BB*SS)   // 1600

// scratch (device globals; no allocation allowed)
__device__ float g_q[NBS*HID];
__device__ float g_k[NBS*HID];
__device__ float g_kpos[NBS*HID];
__device__ float g_vpos[NBS*HID];
__device__ float g_qo[BB*HH*SS];
__device__ float g_ko[BB*HH*SS];
__device__ float g_qd[BB*HH*SS];
__device__ float g_kd[BB*HH*SS];
__device__ float g_probs[NBS*HH*SS];   // normalized probs, [b][i][h][j]
__device__ float g_ctx[NBS*HID];

// ---------------------------------------------------------------------------
// Kernel 1: one (8-row, matrix) tile per block; split-K x4 inside the block.
// (round-3 proven version)
// ---------------------------------------------------------------------------
__global__ __launch_bounds__(256) void gemm3_kernel(
    const float* __restrict__ x,
    const float* __restrict__ Wq, const float* __restrict__ bq,
    const float* __restrict__ Wk, const float* __restrict__ bk,
    const float* __restrict__ Wv, const float* __restrict__ bv,
    const float* __restrict__ posV)
{
    const int r0  = blockIdx.x * 8;
    const int mat = blockIdx.y;
    const float* __restrict__ W    = (mat == 0) ? Wq : (mat == 1) ? Wk : Wv;
    const float* __restrict__ bias = (mat == 0) ? bq : (mat == 1) ? bk : bv;

    const int tid = threadIdx.x;
    const int s   = tid >> 6;
    const int c   = tid & 63;

    __shared__ float xs[HID][8];
    __shared__ float red[3][8][HID];

    for (int t = tid; t < 8 * HID; t += 256) {
        const int m = t >> 8, g = t & 255;
        xs[g][m] = x[(r0 + m) * HID + g];
    }
    __syncthreads();

    float4 acc[8];
    if (s == 0) {
        const float4 b4 = *(const float4*)&bias[4 * c];
        #pragma unroll
        for (int m = 0; m < 8; m++) acc[m] = b4;
    } else {
        #pragma unroll
        for (int m = 0; m < 8; m++) acc[m] = make_float4(0.f, 0.f, 0.f, 0.f);
    }

    const float* __restrict__ Wp = W + (size_t)(s * 64) * HID + 4 * c;
    const float* __restrict__ xp = &xs[s * 64][0];
    #pragma unroll 4
    for (int gi = 0; gi < 64; gi++) {
        const float4 w = *(const float4*)(Wp + (size_t)gi * HID);
        #pragma unroll
        for (int m = 0; m < 8; m++) {
            const float xv = xp[gi * 8 + m];
            acc[m].x += xv * w.x; acc[m].y += xv * w.y;
            acc[m].z += xv * w.z; acc[m].w += xv * w.w;
        }
    }

    if (s > 0) {
        #pragma unroll
        for (int m = 0; m < 8; m++)
            *(float4*)&red[s - 1][m][4 * c] = acc[m];
    }
    __syncthreads();

    if (s == 0) {
        #pragma unroll
        for (int m = 0; m < 8; m++) {
            const float4 r0v = *(const float4*)&red[0][m][4 * c];
            const float4 r1v = *(const float4*)&red[1][m][4 * c];
            const float4 r2v = *(const float4*)&red[2][m][4 * c];
            float4 a = acc[m];
            a.x += r0v.x + r1v.x + r2v.x;
            a.y += r0v.y + r1v.y + r2v.y;
            a.z += r0v.z + r1v.z + r2v.z;
            a.w += r0v.w + r1v.w + r2v.w;
            const int row = r0 + m;
            if (mat == 0) {
                *(float4*)&g_q[(size_t)row * HID + 4 * c] = a;
            } else if (mat == 1) {
                *(float4*)&g_k[(size_t)row * HID + 4 * c] = a;
            } else {
                const float4 pv = *(const float4*)&posV[(size_t)row * HID + 4 * c];
                a.x += pv.x; a.y += pv.y; a.z += pv.z; a.w += pv.w;
                *(float4*)&g_vpos[(size_t)row * HID + 4 * c] = a;
            }
        }
    }
}

// ---------------------------------------------------------------------------
// Kernel 1b: kpos = k + posK; order/dist scalar dot tables. 8 rows/block.
// ---------------------------------------------------------------------------
__global__ __launch_bounds__(256) void post_kernel(
    const float* __restrict__ posK,
    const float* __restrict__ order_w, const float* __restrict__ dist_w)
{
    const int f  = threadIdx.x;
    const int r0 = blockIdx.x * 8;

    __shared__ float qs[8][HID];
    __shared__ float ks[8][HID];

    #pragma unroll
    for (int m = 0; m < 8; m++) {
        const int row = r0 + m;
        const float kv = g_k[(size_t)row * HID + f];
        qs[m][f] = g_q[(size_t)row * HID + f];
        ks[m][f] = kv;
        g_kpos[(size_t)row * HID + f] = kv + posK[(size_t)row * HID + f];
    }
    __syncthreads();

    const int w = f >> 5, l = f & 31;
    const int row = r0 + w;
    const int b = row / SS, sidx = row % SS;
    #pragma unroll
    for (int h = 0; h < HH; h++) {
        float qo = qs[w][h*64 + l] * order_w[l]      + qs[w][h*64 + 32 + l] * order_w[32 + l];
        float qd = qs[w][h*64 + l] * dist_w[l]       + qs[w][h*64 + 32 + l] * dist_w[32 + l];
        float ko = ks[w][h*64 + l] * order_w[64 + l] + ks[w][h*64 + 32 + l] * order_w[96 + l];
        float kd = ks[w][h*64 + l] * dist_w[64 + l]  + ks[w][h*64 + 32 + l] * dist_w[96 + l];
        #pragma unroll
        for (int off = 16; off; off >>= 1) {
            qo += __shfl_xor_sync(0xffffffffu, qo, off);
            qd += __shfl_xor_sync(0xffffffffu, qd, off);
            ko += __shfl_xor_sync(0xffffffffu, ko, off);
            kd += __shfl_xor_sync(0xffffffffu, kd, off);
        }
        if (l == 0) {
            const int idx = (b * HH + h) * SS + sidx;
            g_qo[idx] = qo; g_qd[idx] = qd; g_ko[idx] = ko; g_kd[idx] = kd;
        }
    }
}

// ---------------------------------------------------------------------------
// Kernel 2a: scores + softmax. ITA=2 rows/block, 256 threads, grid 800.
// Simple one-j loop (keeps regs <= 64 for 4 blocks/SM).
// ---------------------------------------------------------------------------
#define ITA 2
__global__ __launch_bounds__(256) void score_kernel(
    const float* __restrict__ timeK,
    const float* __restrict__ mask,
    const float* __restrict__ p_order_b, const float* __restrict__ p_dist_b,
    const float* __restrict__ p_scalar)
{
    const int tid = threadIdx.x;
    const int blk = blockIdx.x;
    const int b  = blk / (SS / ITA);
    const int i0 = (blk % (SS / ITA)) * ITA;
    const int w = tid >> 5, l = tid & 31;

    __shared__ float sc[ITA][HH][SS];
    __shared__ float q_sh[ITA][HID];
    __shared__ float qos[ITA][HH], qds[ITA][HH];
    __shared__ float inv_s[ITA][HH];
    __shared__ float dl[SS];

    #pragma unroll
    for (int it = 0; it < ITA; it++)
        q_sh[it][tid] = g_q[((size_t)(b * SS + i0 + it)) * HID + tid];
    if (tid < ITA * HH) {
        const int it = tid >> 2, h = tid & 3;
        qos[it][h] = g_qo[(b * HH + h) * SS + i0 + it];
        qds[it][h] = g_qd[(b * HH + h) * SS + i0 + it];
    }
    if (tid < SS) dl[tid] = __logf((float)tid + 1.f);
    __syncthreads();

    float4 q0[ITA], q1[ITA];
    #pragma unroll
    for (int it = 0; it < ITA; it++) {
        q0[it] = *(const float4*)&q_sh[it][l * 8];
        q1[it] = *(const float4*)&q_sh[it][l * 8 + 4];
    }
    const int hh = l >> 3;

    const float* tk0 = timeK + ((size_t)(b * SS + i0))     * SS * HID;
    const float* tk1 = timeK + ((size_t)(b * SS + i0 + 1)) * SS * HID;
    const float* kpb = g_kpos + (size_t)b * SS * HID;

    // ---- phase 1: raw scores ----
    for (int j = w; j < SS; j += 8) {
        const float4* kp  = (const float4*)(kpb + (size_t)j * HID);
        const float4* ta0 = (const float4*)(tk0 + (size_t)j * HID);
        const float4* ta1 = (const float4*)(tk1 + (size_t)j * HID);
        const float4 k0 = kp[2 * l],  k1 = kp[2 * l + 1];
        const float4 a0 = ta0[2 * l], a1 = ta0[2 * l + 1];
        const float4 b0 = ta1[2 * l], b1 = ta1[2 * l + 1];

        float p0 = q0[0].x * (a0.x + k0.x) + q0[0].y * (a0.y + k0.y)
                 + q0[0].z * (a0.z + k0.z) + q0[0].w * (a0.w + k0.w)
                 + q1[0].x * (a1.x + k1.x) + q1[0].y * (a1.y + k1.y)
                 + q1[0].z * (a1.z + k1.z) + q1[0].w * (a1.w + k1.w);
        float p1 = q0[1].x * (b0.x + k0.x) + q0[1].y * (b0.y + k0.y)
                 + q0[1].z * (b0.z + k0.z) + q0[1].w * (b0.w + k0.w)
                 + q1[1].x * (b1.x + k1.x) + q1[1].y * (b1.y + k1.y)
                 + q1[1].z * (b1.z + k1.z) + q1[1].w * (b1.w + k1.w);
        p0 += __shfl_xor_sync(0xffffffffu, p0, 1);
        p0 += __shfl_xor_sync(0xffffffffu, p0, 2);
        p0 += __shfl_xor_sync(0xffffffffu, p0, 4);
        p1 += __shfl_xor_sync(0xffffffffu, p1, 1);
        p1 += __shfl_xor_sync(0xffffffffu, p1, 2);
        p1 += __shfl_xor_sync(0xffffffffu, p1, 4);
        if ((l & 7) == 0) { sc[0][hh][j] = p0; sc[1][hh][j] = p1; }
    }
    __syncthreads();

    // ---- phase 2: order/dist error terms, scale, mask ----
    const float order_b = *p_order_b;
    const float dist_b  = *p_dist_b;
    const float sc2 = p_scalar[0] * p_scalar[0] * 0.5f;
    for (int idx = tid; idx < ITA * HH * SS; idx += 256) {
        const int it = idx / (HH * SS);
        const int rem = idx - it * (HH * SS);
        const int h = rem / SS, j = rem - (rem / SS) * SS;
        const int i = i0 + it;
        const float z = qos[it][h] + g_ko[(b * HH + h) * SS + j] + order_b;
        const float zz = (j > i) ? -z : z;     // log-sigmoid via softplus
        const float eo = -(fmaxf(zz, 0.f) + __logf(1.f + __expf(-fabsf(zz))));
        const float gd = dl[abs(j - i)];
        const float pd = qds[it][h] + g_kd[(b * HH + h) * SS + j] + dist_b;
        const float ed = -(gd - pd) * (gd - pd) * sc2;
        sc[it][h][j] = (sc[it][h][j] + eo + ed) * 0.125f
                     + mask[((size_t)b * SS + i) * SS + j];
    }
    __syncthreads();

    // ---- phase 3: softmax (warp per (it,h) pair; 8 warps = 8 pairs) ----
    {
        const int it = w >> 2, h = w & 3;
        float m = -1e30f;
        for (int j = l; j < SS; j += 32) m = fmaxf(m, sc[it][h][j]);
        #pragma unroll
        for (int off = 16; off; off >>= 1)
            m = fmaxf(m, __shfl_xor_sync(0xffffffffu, m, off));
        float sum = 0.f;
        for (int j = l; j < SS; j += 32) {
            const float e = __expf(sc[it][h][j] - m);
            sc[it][h][j] = e;
            sum += e;
        }
        #pragma unroll
        for (int off = 16; off; off >>= 1)
            sum += __shfl_xor_sync(0xffffffffu, sum, off);
        if (l == 0) inv_s[it][h] = 1.f / sum;
    }
    __syncthreads();

    // ---- write normalized probs ----
    for (int idx = tid; idx < ITA * HH * SS; idx += 256) {
        const int it = idx / (HH * SS);
        const int rem = idx - it * (HH * SS);
        const int h = rem / SS, j = rem - (rem / SS) * SS;
        g_probs[((size_t)(b * SS + i0 + it) * HH + h) * SS + j]
            = sc[it][h][j] * inv_s[it][h];
    }
}

// ---------------------------------------------------------------------------
// Kernel 2b: ctx accumulation. ITB=2 rows/block + split-j x2, 256 threads,
// grid 800. Thread = (grp, it, fq); grp g sums j in [100g, 100g+100).
// ---------------------------------------------------------------------------
#define ITB 2
__global__ __launch_bounds__(256) void ctx_kernel(
    const float* __restrict__ timeV)
{
    const int tid = threadIdx.x;
    const int blk = blockIdx.x;
    const int b  = blk / (SS / ITB);
    const int i0 = (blk % (SS / ITB)) * ITB;

    const int grp = tid >> 7;         // j-half 0..1
    const int it  = (tid >> 6) & 1;   // i-row 0..1
    const int fq  = tid & 63;         // float4 index; f = 4*fq
    const int h   = fq >> 4;          // head of this f-quad

    __shared__ float pr[ITB][HH * SS];    // 6.4KB
    __shared__ float4 part[ITB][64];      // 2KB partials from grp 1

    for (int t = tid; t < ITB * HH * SS; t += 256) {
        const int k = t / (HH * SS);
        const int rem = t - k * (HH * SS);
        pr[k][rem] = g_probs[((size_t)(b * SS + i0 + k) * HH) * SS + rem];
    }
    __syncthreads();

    const float4* tv = (const float4*)(timeV + ((size_t)(b * SS + i0 + it)) * SS * HID) + fq;
    const float4* vp = (const float4*)(g_vpos + (size_t)b * SS * HID) + fq;
    const float* prow = &pr[it][h * SS];

    const int j0 = grp * (SS / 2);
    float4 acc = make_float4(0.f, 0.f, 0.f, 0.f);
    #pragma unroll 4
    for (int j = j0; j < j0 + SS / 2; j++) {
        const float p = prow[j];
        const float4 t4 = tv[(size_t)j * (HID / 4)];
        const float4 v4 = vp[(size_t)j * (HID / 4)];
        acc.x += p * (t4.x + v4.x);
        acc.y += p * (t4.y + v4.y);
        acc.z += p * (t4.z + v4.z);
        acc.w += p * (t4.w + v4.w);
    }

    if (grp == 1) part[it][fq] = acc;
    __syncthreads();
    if (grp == 0) {
        const float4 p4 = part[it][fq];
        acc.x += p4.x; acc.y += p4.y; acc.z += p4.z; acc.w += p4.w;
        *(float4*)&g_ctx[((size_t)(b * SS + i0 + it)) * HID + 4 * fq] = acc;
    }
}

// ---------------------------------------------------------------------------
// Kernel 3: output projection, 4 rows/block (grid 400) + residual + LN.
// ---------------------------------------------------------------------------
__global__ __launch_bounds__(256) void outln_kernel(
    const float* __restrict__ x,
    const float* __restrict__ Wd, const float* __restrict__ bd,
    const float* __restrict__ ln_g, const float* __restrict__ ln_b,
    float* __restrict__ out)
{
    const int r0  = blockIdx.x * 4;
    const int tid = threadIdx.x;
    const int s   = tid >> 6;
    const int c   = tid & 63;

    __shared__ float cs[HID][4];
    __shared__ float red[3][4][HID];
    __shared__ float hsm[4][HID];
    __shared__ float mu[4], rstd[4];

    for (int t = tid; t < 4 * HID; t += 256) {
        const int m = t >> 8, g = t & 255;
        cs[g][m] = g_ctx[(size_t)(r0 + m) * HID + g];
    }
    __syncthreads();

    float4 acc[4];
    if (s == 0) {
        const float4 b4 = *(const float4*)&bd[4 * c];
        #pragma unroll
        for (int m = 0; m < 4; m++) acc[m] = b4;
    } else {
        #pragma unroll
        for (int m = 0; m < 4; m++) acc[m] = make_float4(0.f, 0.f, 0.f, 0.f);
    }

    const float* __restrict__ Wp = Wd + (size_t)(s * 64) * HID + 4 * c;
    const float* __restrict__ xp = &cs[s * 64][0];
    #pragma unroll 4
    for (int gi = 0; gi < 64; gi++) {
        const float4 w = *(const float4*)(Wp + (size_t)gi * HID);
        #pragma unroll
        for (int m = 0; m < 4; m++) {
            const float xv = xp[gi * 4 + m];
            acc[m].x += xv * w.x; acc[m].y += xv * w.y;
            acc[m].z += xv * w.z; acc[m].w += xv * w.w;
        }
    }

    if (s > 0) {
        #pragma unroll
        for (int m = 0; m < 4; m++)
            *(float4*)&red[s - 1][m][4 * c] = acc[m];
    }
    __syncthreads();

    if (s == 0) {
        #pragma unroll
        for (int m = 0; m < 4; m++) {
            const float4 p0 = *(const float4*)&red[0][m][4 * c];
            const float4 p1 = *(const float4*)&red[1][m][4 * c];
            const float4 p2 = *(const float4*)&red[2][m][4 * c];
            const float4 xv = *(const float4*)&x[(size_t)(r0 + m) * HID + 4 * c];
            float4 a = acc[m];
            a.x += p0.x + p1.x + p2.x + xv.x;
            a.y += p0.y + p1.y + p2.y + xv.y;
            a.z += p0.z + p1.z + p2.z + xv.z;
            a.w += p0.w + p1.w + p2.w + xv.w;
            *(float4*)&hsm[m][4 * c] = a;
        }
    }
    __syncthreads();

    const int w = tid >> 5, l = tid & 31;
    if (w < 4) {
        float sum = 0.f, sum2 = 0.f;
        #pragma unroll
        for (int t = 0; t < 8; t++) {
            const float v = hsm[w][l + 32 * t];
            sum += v; sum2 += v * v;
        }
        #pragma unroll
        for (int off = 16; off; off >>= 1) {
            sum  += __shfl_xor_sync(0xffffffffu, sum,  off);
            sum2 += __shfl_xor_sync(0xffffffffu, sum2, off);
        }
        if (l == 0) {
            const float m_  = sum / HID;
            const float var = sum2 / HID - m_ * m_;
            mu[w]   = m_;
            rstd[w] = rsqrtf(var + 1e-12f);
        }
    }
    __syncthreads();

    const int f = tid;
    const float gf = ln_g[f], bf = ln_b[f];
    #pragma unroll
    for (int m = 0; m < 4; m++)
        out[(size_t)(r0 + m) * HID + f] = (hsm[m][f] - mu[m]) * rstd[m] * gf + bf;
}

// ---------------------------------------------------------------------------
extern "C" void kernel_launch(void* const* d_in, const int* in_sizes, int n_in,
                              void* d_out, int out_size)
{
    const float* x     = (const float*)d_in[0];
    const float* mask  = (const float*)d_in[1];
    const float* posK  = (const float*)d_in[2];
    const float* posV  = (const float*)d_in[3];
    const float* timeK = (const float*)d_in[4];
    const float* timeV = (const float*)d_in[5];
    const float* Wq = (const float*)d_in[6];  const float* bq = (const float*)d_in[7];
    const float* Wk = (const float*)d_in[8];  const float* bk = (const float*)d_in[9];
    const float* Wv = (const float*)d_in[10]; const float* bv = (const float*)d_in[11];
    const float* ow = (const float*)d_in[12]; const float* ob = (const float*)d_in[13];
    const float* dw = (const float*)d_in[14]; const float* db = (const float*)d_in[15];
    const float* sca = (const float*)d_in[16];
    const float* Wd = (const float*)d_in[17]; const float* bd = (const float*)d_in[18];
    const float* lg = (const float*)d_in[19]; const float* lb = (const float*)d_in[20];

    dim3 g1(NBS / 8, 3);
    gemm3_kernel<<<g1, 256>>>(x, Wq, bq, Wk, bk, Wv, bv, posV);
    post_kernel<<<NBS / 8, 256>>>(posK, ow, dw);
    score_kernel<<<NBS / ITA, 256>>>(timeK, mask, ob, db, sca);
    ctx_kernel<<<NBS / ITB, 256>>>(timeV);
    outln_kernel<<<NBS / 4, 256>>>(x, Wd, bd, lg, lb, (float*)d_out);
}